// round 12
// baseline (speedup 1.0000x reference)
#include <cuda_runtime.h>
#include <cuda_fp16.h>
#include <cstdint>

#define DEVINL __device__ __forceinline__

// Problem constants
static const int Bb = 4, Ss = 4096, Dd = 1024, Hh = 16;

// Scratch (static device globals — allocation-free)
__device__ __align__(1024) __half g_qkvh[16384 * 3072];  // 96 MB fp16 [tokens, 3D]
__device__ __align__(1024) __half g_aoh[16384 * 1024];   // 32 MB fp16 [tokens, D]
__device__ __align__(1024) __half g_rxh[16384 * 1024];
__device__ __align__(1024) __half g_rwh[3072 * 1024];
__device__ __align__(1024) __half g_rwoh[1024 * 1024];

// ---------------------------------------------------------------------------
// helpers
// ---------------------------------------------------------------------------
DEVINL void mma_h(float* c, const uint32_t* a, uint32_t b0, uint32_t b1) {
    asm("mma.sync.aligned.m16n8k16.row.col.f32.f16.f16.f32 "
        "{%0,%1,%2,%3}, {%4,%5,%6,%7}, {%8,%9}, {%0,%1,%2,%3};"
        : "+f"(c[0]), "+f"(c[1]), "+f"(c[2]), "+f"(c[3])
        : "r"(a[0]), "r"(a[1]), "r"(a[2]), "r"(a[3]), "r"(b0), "r"(b1));
}
DEVINL void ldsm4(uint32_t* r, uint32_t addr) {
    asm volatile("ldmatrix.sync.aligned.m8n8.x4.shared.b16 {%0,%1,%2,%3}, [%4];"
        : "=r"(r[0]), "=r"(r[1]), "=r"(r[2]), "=r"(r[3]) : "r"(addr));
}
DEVINL void ldsm4t(uint32_t* r, uint32_t addr) {
    asm volatile("ldmatrix.sync.aligned.m8n8.x4.trans.shared.b16 {%0,%1,%2,%3}, [%4];"
        : "=r"(r[0]), "=r"(r[1]), "=r"(r[2]), "=r"(r[3]) : "r"(addr));
}
DEVINL uint32_t smem_u32(const void* p) { return (uint32_t)__cvta_generic_to_shared(p); }
DEVINL void cp16(uint32_t dst, const void* src) {
    asm volatile("cp.async.ca.shared.global [%0], [%1], 16;" :: "r"(dst), "l"(src));
}
DEVINL void cp_commit() { asm volatile("cp.async.commit_group;"); }
template<int N> DEVINL void cp_wait() { asm volatile("cp.async.wait_group %0;" :: "n"(N)); }
DEVINL void sth2(__half* p, float a, float b) {
    __half2 h = __floats2half2_rn(a, b);
    *(uint32_t*)p = *(const uint32_t*)&h;
}

// ---------------------------------------------------------------------------
// fp32 -> fp16 conversion (RNE)
// ---------------------------------------------------------------------------
__global__ void to_half_k(const float4* __restrict__ in, uint2* __restrict__ out, int n4)
{
    int i = blockIdx.x * blockDim.x + threadIdx.x;
    if (i < n4) {
        float4 v = in[i];
        __half2 h0 = __floats2half2_rn(v.x, v.y);
        __half2 h1 = __floats2half2_rn(v.z, v.w);
        uint2 u;
        u.x = *(const uint32_t*)&h0;
        u.y = *(const uint32_t*)&h1;
        out[i] = u;
    }
}

// ---------------------------------------------------------------------------
// fp16 GEMM: C[M,N] = A[M,K] @ W[N,K]^T + bias[N]
// BM=256, BN=128, BK=64. 256 thr, 8 warps of 64x64 (32 FLOP/smem-byte =
// crossbar/tensor balance). ldmatrix fragments, cp.async double buffer.
// ---------------------------------------------------------------------------
__global__ void __launch_bounds__(256, 1)
gemm_h(const __half* __restrict__ A, int lda,
       const __half* __restrict__ W, int ldw,
       void* __restrict__ Cv, int ldc,
       int K, const float* __restrict__ bias, int half_out)
{
    constexpr int LDH = 72;
    extern __shared__ __half smh[];
    __half* As = smh;                    // [2][256][72]
    __half* Bs = smh + 2 * 256 * LDH;    // [2][128][72]

    const int tid = threadIdx.x, lane = tid & 31, wid = tid >> 5;
    const int warpM = (wid & 3) * 64, warpN = (wid >> 2) * 64;
    const long long m0 = (long long)blockIdx.y * 256;
    const long long n0 = (long long)blockIdx.x * 128;
    const int lr = lane & 15;            // ldmatrix row-within-16
    const int lc = (lane >> 4) * 8;      // ldmatrix col offset

    float acc[4][8][4] = {};

    auto issue = [&](int it, int buf) {
        const long long k0 = (long long)it * 64;
        __half* ad = As + buf * 256 * LDH;
        #pragma unroll
        for (int i = 0; i < 8; ++i) {
            int lin = i * 256 + tid;
            int r = lin >> 3, c8 = (lin & 7) * 8;
            cp16(smem_u32(ad + r * LDH + c8), A + (m0 + r) * lda + k0 + c8);
        }
        __half* bd = Bs + buf * 128 * LDH;
        #pragma unroll
        for (int i = 0; i < 4; ++i) {
            int lin = i * 256 + tid;
            int r = lin >> 3, c8 = (lin & 7) * 8;
            cp16(smem_u32(bd + r * LDH + c8), W + (n0 + r) * ldw + k0 + c8);
        }
        cp_commit();
    };

    const int NIT = K / 64;
    issue(0, 0);
    int buf = 0;
    for (int it = 0; it < NIT; ++it) {
        cp_wait<0>();
        __syncthreads();
        if (it + 1 < NIT) issue(it + 1, buf ^ 1);

        const __half* a = As + buf * 256 * LDH;
        const __half* b = Bs + buf * 128 * LDH;
        #pragma unroll
        for (int k16 = 0; k16 < 4; ++k16) {
            const int kb = k16 * 16 + lc;
            uint32_t af[4][4], bf[4][4];
            #pragma unroll
            for (int im = 0; im < 4; ++im)
                ldsm4(af[im], smem_u32(a + (warpM + im * 16 + lr) * LDH + kb));
            #pragma unroll
            for (int in = 0; in < 4; ++in)
                ldsm4(bf[in], smem_u32(b + (warpN + in * 16 + lr) * LDH + kb));
            #pragma unroll
            for (int in = 0; in < 4; ++in)
                #pragma unroll
                for (int im = 0; im < 4; ++im) {
                    mma_h(acc[im][2 * in],     af[im], bf[in][0], bf[in][2]);
                    mma_h(acc[im][2 * in + 1], af[im], bf[in][1], bf[in][3]);
                }
        }
        buf ^= 1;
    }

    #pragma unroll
    for (int im = 0; im < 4; ++im) {
        long long r = m0 + warpM + im * 16 + (lane >> 2);
        #pragma unroll
        for (int in = 0; in < 8; ++in) {
            long long c = n0 + warpN + in * 8 + 2 * (lane & 3);
            float b0 = bias[c], b1 = bias[c + 1];
            float v0 = acc[im][in][0] + b0, v1 = acc[im][in][1] + b1;
            float v2 = acc[im][in][2] + b0, v3 = acc[im][in][3] + b1;
            if (half_out) {
                __half* Ch = (__half*)Cv;
                sth2(Ch + r * ldc + c, v0, v1);
                sth2(Ch + (r + 8) * ldc + c, v2, v3);
            } else {
                float* Cf = (float*)Cv;
                *(float2*)&Cf[r * ldc + c]       = make_float2(v0, v1);
                *(float2*)&Cf[(r + 8) * ldc + c] = make_float2(v2, v3);
            }
        }
    }
}

// ---------------------------------------------------------------------------
// Fused fp16 attention, ldmatrix edition. TM = Q-rows/warp (16 local, 32 glob).
// Q fragments hoisted to registers once. V via ldmatrix.trans (no transpose).
// smem halves: sQ[QT][72] | sP[QT][72] | sK[2][64][72] | sV[2][64][72]
// ---------------------------------------------------------------------------
template<int TM>
__global__ void __launch_bounds__(256, 1)
attn_h(const __half* __restrict__ qkv, __half* __restrict__ ao, int W, int nc)
{
    constexpr int QT = TM * 8;
    constexpr int MT = TM / 16;
    constexpr int NH = TM / 8;
    constexpr int LDH = 72;
    extern __shared__ __half smh[];
    __half* sQ = smh;                         // QT x 72
    __half* sP = sQ + QT * LDH;               // QT x 72
    __half* sK = sP + QT * LDH;               // 2 x 64 x 72
    __half* sV = sK + 2 * 64 * LDH;           // 2 x 64 x 72

    const int tid = threadIdx.x, lane = tid & 31, wid = tid >> 5;
    const int wm = wid * TM;
    const int lr = lane & 15, lc = (lane >> 4) * 8;
    const int vkr = (lane & 7) + ((lane >> 4) & 1) * 8;   // V-trans key row
    const int vdc = ((lane >> 3) & 1) * 8;                // V-trans dim col
    const int pair = blockIdx.y;
    const int win = pair >> 4, h = pair & 15;
    const int q0 = blockIdx.x * QT;
    const long long base = (long long)win * W * 3072 + h * 64;
    const __half* Qg = qkv + base + (long long)q0 * 3072;
    const __half* Kg = qkv + base + 1024;
    const __half* Vg = qkv + base + 2048;

    // stage Q
    #pragma unroll
    for (int i = 0; i < QT / 32; ++i) {
        int lin = i * 256 + tid;
        int r = lin >> 3, c8 = (lin & 7) * 8;
        cp16(smem_u32(sQ + r * LDH + c8), Qg + (long long)r * 3072 + c8);
    }
    cp_commit();

    auto stageKV = [&](int c, int b) {
        #pragma unroll
        for (int i = 0; i < 2; ++i) {
            int lin = i * 256 + tid;
            int r = lin >> 3, c8 = (lin & 7) * 8;
            cp16(smem_u32(sK + b * 64 * LDH + r * LDH + c8),
                 Kg + (long long)(c * 64 + r) * 3072 + c8);
        }
        #pragma unroll
        for (int i = 0; i < 2; ++i) {
            int lin = i * 256 + tid;
            int r = lin >> 3, c8 = (lin & 7) * 8;
            cp16(smem_u32(sV + b * 64 * LDH + r * LDH + c8),
                 Vg + (long long)(c * 64 + r) * 3072 + c8);
        }
        cp_commit();
    };
    stageKV(0, 0);

    // Q arrived (1 group may remain pending) -> hoist Q fragments to registers
    cp_wait<1>();
    __syncthreads();
    uint32_t qf[MT][4][4];
    #pragma unroll
    for (int im = 0; im < MT; ++im)
        #pragma unroll
        for (int k16 = 0; k16 < 4; ++k16)
            ldsm4(qf[im][k16],
                  smem_u32(sQ + (wm + im * 16 + lr) * LDH + k16 * 16 + lc));

    float oacc[MT][8][4] = {};
    float m_[NH], l_[NH];
    #pragma unroll
    for (int i = 0; i < NH; ++i) { m_[i] = -1e30f; l_[i] = 0.f; }

    for (int c = 0; c < nc; ++c) {
        const int buf = c & 1;
        if (c + 1 < nc) { stageKV(c + 1, buf ^ 1); cp_wait<1>(); }
        else            { cp_wait<0>(); }
        __syncthreads();

        const __half* kbuf = sK + buf * 64 * LDH;
        const __half* vbuf = sV + buf * 64 * LDH;

        // ---- S = Q K^T ----
        float sacc[MT][8][4];
        #pragma unroll
        for (int im = 0; im < MT; ++im)
            #pragma unroll
            for (int in = 0; in < 8; ++in)
                sacc[im][in][0] = sacc[im][in][1] = sacc[im][in][2] = sacc[im][in][3] = 0.f;

        #pragma unroll
        for (int k16 = 0; k16 < 4; ++k16) {
            const int kb = k16 * 16 + lc;
            #pragma unroll
            for (int nb = 0; nb < 4; ++nb) {
                uint32_t bf[4];
                ldsm4(bf, smem_u32(kbuf + (nb * 16 + lr) * LDH + kb));
                #pragma unroll
                for (int im = 0; im < MT; ++im) {
                    mma_h(sacc[im][2 * nb],     qf[im][k16], bf[0], bf[2]);
                    mma_h(sacc[im][2 * nb + 1], qf[im][k16], bf[1], bf[3]);
                }
            }
        }

        // ---- online softmax (ADDITIVE +1.0 mask for col > row) ----
        float sscale[NH];
        #pragma unroll
        for (int hh = 0; hh < NH; ++hh) {
            const int im = hh >> 1, half = hh & 1;
            const int rw = q0 + wm + im * 16 + (lane >> 2) + 8 * half;
            float cm = -1e30f;
            #pragma unroll
            for (int in = 0; in < 8; ++in) {
                int col = c * 64 + in * 8 + 2 * (lane & 3);
                float v0 = sacc[im][in][2 * half]     * 0.125f + ((col     > rw) ? 1.f : 0.f);
                float v1 = sacc[im][in][2 * half + 1] * 0.125f + ((col + 1 > rw) ? 1.f : 0.f);
                sacc[im][in][2 * half] = v0; sacc[im][in][2 * half + 1] = v1;
                cm = fmaxf(cm, fmaxf(v0, v1));
            }
            cm = fmaxf(cm, __shfl_xor_sync(0xffffffffu, cm, 1));
            cm = fmaxf(cm, __shfl_xor_sync(0xffffffffu, cm, 2));
            float mn = fmaxf(m_[hh], cm);
            float sc = __expf(m_[hh] - mn);
            float rs = 0.f;
            const int rloc = wm + im * 16 + (lane >> 2) + 8 * half;
            #pragma unroll
            for (int in = 0; in < 8; ++in) {
                float p0 = __expf(sacc[im][in][2 * half] - mn);
                float p1 = __expf(sacc[im][in][2 * half + 1] - mn);
                rs += p0 + p1;
                sth2(sP + rloc * LDH + in * 8 + 2 * (lane & 3), p0, p1);
            }
            rs += __shfl_xor_sync(0xffffffffu, rs, 1);
            rs += __shfl_xor_sync(0xffffffffu, rs, 2);
            l_[hh] = l_[hh] * sc + rs;
            m_[hh] = mn;
            sscale[hh] = sc;
        }
        #pragma unroll
        for (int im = 0; im < MT; ++im)
            #pragma unroll
            for (int in = 0; in < 8; ++in) {
                oacc[im][in][0] *= sscale[2 * im];
                oacc[im][in][1] *= sscale[2 * im];
                oacc[im][in][2] *= sscale[2 * im + 1];
                oacc[im][in][3] *= sscale[2 * im + 1];
            }
        __syncwarp();   // sP rows are warp-private; ldmatrix reads cross-lane

        // ---- O += P V (V via ldmatrix.trans; k = 64 keys) ----
        #pragma unroll
        for (int k16 = 0; k16 < 4; ++k16) {
            const int kb = k16 * 16;
            uint32_t pf[MT][4];
            #pragma unroll
            for (int im = 0; im < MT; ++im)
                ldsm4(pf[im], smem_u32(sP + (wm + im * 16 + lr) * LDH + kb + lc));
            #pragma unroll
            for (int d16 = 0; d16 < 4; ++d16) {
                uint32_t vf[4];
                ldsm4t(vf, smem_u32(vbuf + (kb + vkr) * LDH + d16 * 16 + vdc));
                #pragma unroll
                for (int im = 0; im < MT; ++im) {
                    mma_h(oacc[im][2 * d16],     pf[im], vf[0], vf[2]);
                    mma_h(oacc[im][2 * d16 + 1], pf[im], vf[1], vf[3]);
                }
            }
        }
        __syncthreads();   // all reads done before next stage overwrites buffers
    }

    // ---- epilogue: O /= l -> fp16 ao ----
    #pragma unroll
    for (int im = 0; im < MT; ++im)
        #pragma unroll
        for (int half = 0; half < 2; ++half) {
            const int hh = 2 * im + half;
            const float inv = 1.f / l_[hh];
            const long long trow = (long long)win * W + q0 + wm + im * 16
                                   + (lane >> 2) + 8 * half;
            __half* Od = ao + trow * 1024 + h * 64;
            #pragma unroll
            for (int in = 0; in < 8; ++in) {
                int cc = in * 8 + 2 * (lane & 3);
                sth2(Od + cc, oacc[im][in][2 * half] * inv,
                              oacc[im][in][2 * half + 1] * inv);
            }
        }
}

// ---------------------------------------------------------------------------
// driver
// ---------------------------------------------------------------------------
static const int GEMM_SMEM = 2 * (256 + 128) * 72 * 2;            // 110592
static const int ATTN16_SMEM = (2 * 128 + 4 * 64) * 72 * 2;       // 73728
static const int ATTN32_SMEM = (2 * 256 + 4 * 64) * 72 * 2;       // 110592

static void run_branch(const float* x, const float* w_in, const float* b_in,
                       const float* w_out, const float* b_out,
                       int W, float* out,
                       __half* qkv, __half* ao, __half* rX, __half* rW, __half* rWo)
{
    to_half_k<<<16384, 256>>>((const float4*)x, (uint2*)rX, 16384 * 1024 / 4);
    to_half_k<<<3072, 256>>>((const float4*)w_in, (uint2*)rW, 3072 * 1024 / 4);
    to_half_k<<<1024, 256>>>((const float4*)w_out, (uint2*)rWo, 1024 * 1024 / 4);

    gemm_h<<<dim3(3072 / 128, 16384 / 256), 256, GEMM_SMEM>>>(
        rX, Dd, rW, Dd, qkv, 3072, Dd, b_in, 1);

    if (W == 128)
        attn_h<16><<<dim3(1, (16384 / 128) * Hh), 256, ATTN16_SMEM>>>(qkv, ao, W, 2);
    else
        attn_h<32><<<dim3(W / 256, (16384 / W) * Hh), 256, ATTN32_SMEM>>>(qkv, ao, W, 16);

    gemm_h<<<dim3(1024 / 128, 16384 / 256), 256, GEMM_SMEM>>>(
        ao, Dd, rWo, Dd, out, Dd, Dd, b_out, 0);
}

extern "C" void kernel_launch(void* const* d_in, const int* in_sizes, int n_in,
                              void* d_out, int out_size)
{
    const float* lqs    = (const float*)d_in[0];
    const float* gqs    = (const float*)d_in[1];
    const float* wl_in  = (const float*)d_in[2];
    const float* bl_in  = (const float*)d_in[3];
    const float* wl_out = (const float*)d_in[4];
    const float* bl_out = (const float*)d_in[5];
    const float* wg_in  = (const float*)d_in[6];
    const float* bg_in  = (const float*)d_in[7];
    const float* wg_out = (const float*)d_in[8];
    const float* bg_out = (const float*)d_in[9];
    float* out = (float*)d_out;

    cudaFuncSetAttribute(gemm_h, cudaFuncAttributeMaxDynamicSharedMemorySize, GEMM_SMEM);
    cudaFuncSetAttribute(attn_h<16>, cudaFuncAttributeMaxDynamicSharedMemorySize, ATTN16_SMEM);
    cudaFuncSetAttribute(attn_h<32>, cudaFuncAttributeMaxDynamicSharedMemorySize, ATTN32_SMEM);

    __half *qkv, *ao, *rX, *rW, *rWo;
    cudaGetSymbolAddress((void**)&qkv, g_qkvh);
    cudaGetSymbolAddress((void**)&ao, g_aoh);
    cudaGetSymbolAddress((void**)&rX, g_rxh);
    cudaGetSymbolAddress((void**)&rW, g_rwh);
    cudaGetSymbolAddress((void**)&rWo, g_rwoh);

    run_branch(lqs, wl_in, bl_in, wl_out, bl_out, 128, out, qkv, ao, rX, rW, rWo);
    run_branch(gqs, wg_in, bg_in, wg_out, bg_out, 1024,
               out + (size_t)Bb * Ss * Dd, qkv, ao, rX, rW, rWo);
}

// round 14
// speedup vs baseline: 1.0653x; 1.0653x over previous
#include <cuda_runtime.h>
#include <cuda_fp16.h>
#include <cstdint>

#define DEVINL __device__ __forceinline__

// Problem constants
static const int Bb = 4, Ss = 4096, Dd = 1024, Hh = 16;

// Scratch (static device globals — allocation-free)
__device__ __align__(1024) __half g_qkvh[16384 * 3072];  // 96 MB fp16 [tokens, 3D]
__device__ __align__(1024) __half g_aoh[16384 * 1024];   // 32 MB fp16 [tokens, D]
__device__ __align__(1024) __half g_rxh[16384 * 1024];
__device__ __align__(1024) __half g_rwh[3072 * 1024];
__device__ __align__(1024) __half g_rwoh[1024 * 1024];

// ---------------------------------------------------------------------------
// helpers
// ---------------------------------------------------------------------------
DEVINL void mma_h(float* c, const uint32_t* a, uint32_t b0, uint32_t b1) {
    asm("mma.sync.aligned.m16n8k16.row.col.f32.f16.f16.f32 "
        "{%0,%1,%2,%3}, {%4,%5,%6,%7}, {%8,%9}, {%0,%1,%2,%3};"
        : "+f"(c[0]), "+f"(c[1]), "+f"(c[2]), "+f"(c[3])
        : "r"(a[0]), "r"(a[1]), "r"(a[2]), "r"(a[3]), "r"(b0), "r"(b1));
}
DEVINL void ldsm4(uint32_t* r, uint32_t addr) {
    asm volatile("ldmatrix.sync.aligned.m8n8.x4.shared.b16 {%0,%1,%2,%3}, [%4];"
        : "=r"(r[0]), "=r"(r[1]), "=r"(r[2]), "=r"(r[3]) : "r"(addr));
}
DEVINL void ldsm4t(uint32_t* r, uint32_t addr) {
    asm volatile("ldmatrix.sync.aligned.m8n8.x4.trans.shared.b16 {%0,%1,%2,%3}, [%4];"
        : "=r"(r[0]), "=r"(r[1]), "=r"(r[2]), "=r"(r[3]) : "r"(addr));
}
DEVINL uint32_t smem_u32(const void* p) { return (uint32_t)__cvta_generic_to_shared(p); }
DEVINL void cp16(uint32_t dst, const void* src) {
    asm volatile("cp.async.ca.shared.global [%0], [%1], 16;" :: "r"(dst), "l"(src));
}
DEVINL void cp_commit() { asm volatile("cp.async.commit_group;"); }
template<int N> DEVINL void cp_wait() { asm volatile("cp.async.wait_group %0;" :: "n"(N)); }
DEVINL void sth2(__half* p, float a, float b) {
    __half2 h = __floats2half2_rn(a, b);
    *(uint32_t*)p = *(const uint32_t*)&h;
}

// ---------------------------------------------------------------------------
// fp32 -> fp16 conversion (RNE)
// ---------------------------------------------------------------------------
__global__ void to_half_k(const float4* __restrict__ in, uint2* __restrict__ out, int n4)
{
    int i = blockIdx.x * blockDim.x + threadIdx.x;
    if (i < n4) {
        float4 v = in[i];
        __half2 h0 = __floats2half2_rn(v.x, v.y);
        __half2 h1 = __floats2half2_rn(v.z, v.w);
        uint2 u;
        u.x = *(const uint32_t*)&h0;
        u.y = *(const uint32_t*)&h1;
        out[i] = u;
    }
}

// ---------------------------------------------------------------------------
// fp16 GEMM: C[M,N] = A[M,K] @ W[N,K]^T + bias[N]
// BM=128, BN=128, BK=64. 256 thr, 8 warps of 32x64, ldmatrix fragments,
// __launch_bounds__(256,2) -> 2 CTAs/SM = 16 warps (the r11 occupancy that
// won) + r12's LDSM issue savings. cp.async double buffer.
// ---------------------------------------------------------------------------
__global__ void __launch_bounds__(256, 2)
gemm_h(const __half* __restrict__ A, int lda,
       const __half* __restrict__ W, int ldw,
       void* __restrict__ Cv, int ldc,
       int K, const float* __restrict__ bias, int half_out)
{
    constexpr int LDH = 72;
    extern __shared__ __half smh[];
    __half* As = smh;                    // [2][128][72]
    __half* Bs = smh + 2 * 128 * LDH;    // [2][128][72]

    const int tid = threadIdx.x, lane = tid & 31, wid = tid >> 5;
    const int warpM = (wid & 3) * 32, warpN = (wid >> 2) * 64;
    const long long m0 = (long long)blockIdx.y * 128;
    const long long n0 = (long long)blockIdx.x * 128;
    const int lr = lane & 15;            // ldmatrix row-within-16
    const int lc = (lane >> 4) * 8;      // ldmatrix col offset

    float acc[2][8][4] = {};

    auto issue = [&](int it, int buf) {
        const long long k0 = (long long)it * 64;
        __half* ad = As + buf * 128 * LDH;
        #pragma unroll
        for (int i = 0; i < 4; ++i) {
            int lin = i * 256 + tid;
            int r = lin >> 3, c8 = (lin & 7) * 8;
            cp16(smem_u32(ad + r * LDH + c8), A + (m0 + r) * lda + k0 + c8);
        }
        __half* bd = Bs + buf * 128 * LDH;
        #pragma unroll
        for (int i = 0; i < 4; ++i) {
            int lin = i * 256 + tid;
            int r = lin >> 3, c8 = (lin & 7) * 8;
            cp16(smem_u32(bd + r * LDH + c8), W + (n0 + r) * ldw + k0 + c8);
        }
        cp_commit();
    };

    const int NIT = K / 64;
    issue(0, 0);
    int buf = 0;
    for (int it = 0; it < NIT; ++it) {
        cp_wait<0>();
        __syncthreads();
        if (it + 1 < NIT) issue(it + 1, buf ^ 1);

        const __half* a = As + buf * 128 * LDH;
        const __half* b = Bs + buf * 128 * LDH;
        #pragma unroll
        for (int k16 = 0; k16 < 4; ++k16) {
            const int kb = k16 * 16 + lc;
            uint32_t af[2][4], bf[4][4];
            #pragma unroll
            for (int im = 0; im < 2; ++im)
                ldsm4(af[im], smem_u32(a + (warpM + im * 16 + lr) * LDH + kb));
            #pragma unroll
            for (int in = 0; in < 4; ++in)
                ldsm4(bf[in], smem_u32(b + (warpN + in * 16 + lr) * LDH + kb));
            #pragma unroll
            for (int in = 0; in < 4; ++in)
                #pragma unroll
                for (int im = 0; im < 2; ++im) {
                    mma_h(acc[im][2 * in],     af[im], bf[in][0], bf[in][2]);
                    mma_h(acc[im][2 * in + 1], af[im], bf[in][1], bf[in][3]);
                }
        }
        buf ^= 1;
    }

    #pragma unroll
    for (int im = 0; im < 2; ++im) {
        long long r = m0 + warpM + im * 16 + (lane >> 2);
        #pragma unroll
        for (int in = 0; in < 8; ++in) {
            long long c = n0 + warpN + in * 8 + 2 * (lane & 3);
            float b0 = bias[c], b1 = bias[c + 1];
            float v0 = acc[im][in][0] + b0, v1 = acc[im][in][1] + b1;
            float v2 = acc[im][in][2] + b0, v3 = acc[im][in][3] + b1;
            if (half_out) {
                __half* Ch = (__half*)Cv;
                sth2(Ch + r * ldc + c, v0, v1);
                sth2(Ch + (r + 8) * ldc + c, v2, v3);
            } else {
                float* Cf = (float*)Cv;
                *(float2*)&Cf[r * ldc + c]       = make_float2(v0, v1);
                *(float2*)&Cf[(r + 8) * ldc + c] = make_float2(v2, v3);
            }
        }
    }
}

// ---------------------------------------------------------------------------
// Fused fp16 attention (r12 structure). TM = Q-rows/warp (16 local, 32 glob).
// Q fragments hoisted to registers once. V via ldmatrix.trans.
// smem halves: sQ[QT][72] | sP[QT][72] | sK[2][64][72] | sV[2][64][72]
// ---------------------------------------------------------------------------
template<int TM>
__global__ void __launch_bounds__(256, 1)
attn_h(const __half* __restrict__ qkv, __half* __restrict__ ao, int W, int nc)
{
    constexpr int QT = TM * 8;
    constexpr int MT = TM / 16;
    constexpr int NH = TM / 8;
    constexpr int LDH = 72;
    extern __shared__ __half smh[];
    __half* sQ = smh;                         // QT x 72
    __half* sP = sQ + QT * LDH;               // QT x 72
    __half* sK = sP + QT * LDH;               // 2 x 64 x 72
    __half* sV = sK + 2 * 64 * LDH;           // 2 x 64 x 72

    const int tid = threadIdx.x, lane = tid & 31, wid = tid >> 5;
    const int wm = wid * TM;
    const int lr = lane & 15, lc = (lane >> 4) * 8;
    const int vkr = (lane & 7) + ((lane >> 4) & 1) * 8;   // V-trans key row
    const int vdc = ((lane >> 3) & 1) * 8;                // V-trans dim col
    const int pair = blockIdx.y;
    const int win = pair >> 4, h = pair & 15;
    const int q0 = blockIdx.x * QT;
    const long long base = (long long)win * W * 3072 + h * 64;
    const __half* Qg = qkv + base + (long long)q0 * 3072;
    const __half* Kg = qkv + base + 1024;
    const __half* Vg = qkv + base + 2048;

    // stage Q
    #pragma unroll
    for (int i = 0; i < QT / 32; ++i) {
        int lin = i * 256 + tid;
        int r = lin >> 3, c8 = (lin & 7) * 8;
        cp16(smem_u32(sQ + r * LDH + c8), Qg + (long long)r * 3072 + c8);
    }
    cp_commit();

    auto stageKV = [&](int c, int b) {
        #pragma unroll
        for (int i = 0; i < 2; ++i) {
            int lin = i * 256 + tid;
            int r = lin >> 3, c8 = (lin & 7) * 8;
            cp16(smem_u32(sK + b * 64 * LDH + r * LDH + c8),
                 Kg + (long long)(c * 64 + r) * 3072 + c8);
        }
        #pragma unroll
        for (int i = 0; i < 2; ++i) {
            int lin = i * 256 + tid;
            int r = lin >> 3, c8 = (lin & 7) * 8;
            cp16(smem_u32(sV + b * 64 * LDH + r * LDH + c8),
                 Vg + (long long)(c * 64 + r) * 3072 + c8);
        }
        cp_commit();
    };
    stageKV(0, 0);

    // Q arrived -> hoist Q fragments to registers
    cp_wait<1>();
    __syncthreads();
    uint32_t qf[MT][4][4];
    #pragma unroll
    for (int im = 0; im < MT; ++im)
        #pragma unroll
        for (int k16 = 0; k16 < 4; ++k16)
            ldsm4(qf[im][k16],
                  smem_u32(sQ + (wm + im * 16 + lr) * LDH + k16 * 16 + lc));

    float oacc[MT][8][4] = {};
    float m_[NH], l_[NH];
    #pragma unroll
    for (int i = 0; i < NH; ++i) { m_[i] = -1e30f; l_[i] = 0.f; }

    for (int c = 0; c < nc; ++c) {
        const int buf = c & 1;
        if (c + 1 < nc) { stageKV(c + 1, buf ^ 1); cp_wait<1>(); }
        else            { cp_wait<0>(); }
        __syncthreads();

        const __half* kbuf = sK + buf * 64 * LDH;
        const __half* vbuf = sV + buf * 64 * LDH;

        // ---- S = Q K^T ----
        float sacc[MT][8][4];
        #pragma unroll
        for (int im = 0; im < MT; ++im)
            #pragma unroll
            for (int in = 0; in < 8; ++in)
                sacc[im][in][0] = sacc[im][in][1] = sacc[im][in][2] = sacc[im][in][3] = 0.f;

        #pragma unroll
        for (int k16 = 0; k16 < 4; ++k16) {
            const int kb = k16 * 16 + lc;
            #pragma unroll
            for (int nb = 0; nb < 4; ++nb) {
                uint32_t bf[4];
                ldsm4(bf, smem_u32(kbuf + (nb * 16 + lr) * LDH + kb));
                #pragma unroll
                for (int im = 0; im < MT; ++im) {
                    mma_h(sacc[im][2 * nb],     qf[im][k16], bf[0], bf[2]);
                    mma_h(sacc[im][2 * nb + 1], qf[im][k16], bf[1], bf[3]);
                }
            }
        }

        // ---- online softmax (ADDITIVE +1.0 mask for col > row) ----
        float sscale[NH];
        #pragma unroll
        for (int hh = 0; hh < NH; ++hh) {
            const int im = hh >> 1, half = hh & 1;
            const int rw = q0 + wm + im * 16 + (lane >> 2) + 8 * half;
            float cm = -1e30f;
            #pragma unroll
            for (int in = 0; in < 8; ++in) {
                int col = c * 64 + in * 8 + 2 * (lane & 3);
                float v0 = sacc[im][in][2 * half]     * 0.125f + ((col     > rw) ? 1.f : 0.f);
                float v1 = sacc[im][in][2 * half + 1] * 0.125f + ((col + 1 > rw) ? 1.f : 0.f);
                sacc[im][in][2 * half] = v0; sacc[im][in][2 * half + 1] = v1;
                cm = fmaxf(cm, fmaxf(v0, v1));
            }
            cm = fmaxf(cm, __shfl_xor_sync(0xffffffffu, cm, 1));
            cm = fmaxf(cm, __shfl_xor_sync(0xffffffffu, cm, 2));
            float mn = fmaxf(m_[hh], cm);
            float sc = __expf(m_[hh] - mn);
            float rs = 0.f;
            const int rloc = wm + im * 16 + (lane >> 2) + 8 * half;
            #pragma unroll
            for (int in = 0; in < 8; ++in) {
                float p0 = __expf(sacc[im][in][2 * half] - mn);
                float p1 = __expf(sacc[im][in][2 * half + 1] - mn);
                rs += p0 + p1;
                sth2(sP + rloc * LDH + in * 8 + 2 * (lane & 3), p0, p1);
            }
            rs += __shfl_xor_sync(0xffffffffu, rs, 1);
            rs += __shfl_xor_sync(0xffffffffu, rs, 2);
            l_[hh] = l_[hh] * sc + rs;
            m_[hh] = mn;
            sscale[hh] = sc;
        }
        #pragma unroll
        for (int im = 0; im < MT; ++im)
            #pragma unroll
            for (int in = 0; in < 8; ++in) {
                oacc[im][in][0] *= sscale[2 * im];
                oacc[im][in][1] *= sscale[2 * im];
                oacc[im][in][2] *= sscale[2 * im + 1];
                oacc[im][in][3] *= sscale[2 * im + 1];
            }
        __syncwarp();   // sP rows warp-private; ldmatrix reads cross-lane

        // ---- O += P V (V via ldmatrix.trans) ----
        #pragma unroll
        for (int k16 = 0; k16 < 4; ++k16) {
            const int kb = k16 * 16;
            uint32_t pf[MT][4];
            #pragma unroll
            for (int im = 0; im < MT; ++im)
                ldsm4(pf[im], smem_u32(sP + (wm + im * 16 + lr) * LDH + kb + lc));
            #pragma unroll
            for (int d16 = 0; d16 < 4; ++d16) {
                uint32_t vf[4];
                ldsm4t(vf, smem_u32(vbuf + (kb + vkr) * LDH + d16 * 16 + vdc));
                #pragma unroll
                for (int im = 0; im < MT; ++im) {
                    mma_h(oacc[im][2 * d16],     pf[im], vf[0], vf[2]);
                    mma_h(oacc[im][2 * d16 + 1], pf[im], vf[1], vf[3]);
                }
            }
        }
        __syncthreads();
    }

    // ---- epilogue: O /= l -> fp16 ao ----
    #pragma unroll
    for (int im = 0; im < MT; ++im)
        #pragma unroll
        for (int half = 0; half < 2; ++half) {
            const int hh = 2 * im + half;
            const float inv = 1.f / l_[hh];
            const long long trow = (long long)win * W + q0 + wm + im * 16
                                   + (lane >> 2) + 8 * half;
            __half* Od = ao + trow * 1024 + h * 64;
            #pragma unroll
            for (int in = 0; in < 8; ++in) {
                int cc = in * 8 + 2 * (lane & 3);
                sth2(Od + cc, oacc[im][in][2 * half] * inv,
                              oacc[im][in][2 * half + 1] * inv);
            }
        }
}

// ---------------------------------------------------------------------------
// driver
// ---------------------------------------------------------------------------
static const int GEMM_SMEM = 2 * (128 + 128) * 72 * 2;            // 73728
static const int ATTN16_SMEM = (2 * 128 + 4 * 64) * 72 * 2;       // 73728
static const int ATTN32_SMEM = (2 * 256 + 4 * 64) * 72 * 2;       // 110592

static void run_branch(const float* x, const float* w_in, const float* b_in,
                       const float* w_out, const float* b_out,
                       int W, float* out,
                       __half* qkv, __half* ao, __half* rX, __half* rW, __half* rWo)
{
    to_half_k<<<16384, 256>>>((const float4*)x, (uint2*)rX, 16384 * 1024 / 4);
    to_half_k<<<3072, 256>>>((const float4*)w_in, (uint2*)rW, 3072 * 1024 / 4);
    to_half_k<<<1024, 256>>>((const float4*)w_out, (uint2*)rWo, 1024 * 1024 / 4);

    gemm_h<<<dim3(3072 / 128, 16384 / 128), 256, GEMM_SMEM>>>(
        rX, Dd, rW, Dd, qkv, 3072, Dd, b_in, 1);

    if (W == 128)
        attn_h<16><<<dim3(1, (16384 / 128) * Hh), 256, ATTN16_SMEM>>>(qkv, ao, W, 2);
    else
        attn_h<32><<<dim3(W / 256, (16384 / W) * Hh), 256, ATTN32_SMEM>>>(qkv, ao, W, 16);

    gemm_h<<<dim3(1024 / 128, 16384 / 128), 256, GEMM_SMEM>>>(
        ao, Dd, rWo, Dd, out, Dd, Dd, b_out, 0);
}

extern "C" void kernel_launch(void* const* d_in, const int* in_sizes, int n_in,
                              void* d_out, int out_size)
{
    const float* lqs    = (const float*)d_in[0];
    const float* gqs    = (const float*)d_in[1];
    const float* wl_in  = (const float*)d_in[2];
    const float* bl_in  = (const float*)d_in[3];
    const float* wl_out = (const float*)d_in[4];
    const float* bl_out = (const float*)d_in[5];
    const float* wg_in  = (const float*)d_in[6];
    const float* bg_in  = (const float*)d_in[7];
    const float* wg_out = (const float*)d_in[8];
    const float* bg_out = (const float*)d_in[9];
    float* out = (float*)d_out;

    cudaFuncSetAttribute(gemm_h, cudaFuncAttributeMaxDynamicSharedMemorySize, GEMM_SMEM);
    cudaFuncSetAttribute(attn_h<16>, cudaFuncAttributeMaxDynamicSharedMemorySize, ATTN16_SMEM);
    cudaFuncSetAttribute(attn_h<32>, cudaFuncAttributeMaxDynamicSharedMemorySize, ATTN32_SMEM);

    __half *qkv, *ao, *rX, *rW, *rWo;
    cudaGetSymbolAddress((void**)&qkv, g_qkvh);
    cudaGetSymbolAddress((void**)&ao, g_aoh);
    cudaGetSymbolAddress((void**)&rX, g_rxh);
    cudaGetSymbolAddress((void**)&rW, g_rwh);
    cudaGetSymbolAddress((void**)&rWo, g_rwoh);

    run_branch(lqs, wl_in, bl_in, wl_out, bl_out, 128, out, qkv, ao, rX, rW, rWo);
    run_branch(gqs, wg_in, bg_in, wg_out, bg_out, 1024,
               out + (size_t)Bb * Ss * Dd, qkv, ao, rX, rW, rWo);
}

// round 15
// speedup vs baseline: 1.1440x; 1.0739x over previous
#include <cuda_runtime.h>
#include <cuda_fp16.h>
#include <cstdint>

#define DEVINL __device__ __forceinline__

// Problem constants
static const int Bb = 4, Ss = 4096, Dd = 1024, Hh = 16;

// Per-branch scratch (branch 0 = local, 1 = global)
__device__ __align__(1024) __half g_qkvh[2][16384 * 3072];  // 192 MB
__device__ __align__(1024) __half g_aoh[2][16384 * 1024];   // 64 MB
__device__ __align__(1024) __half g_rxh[2][16384 * 1024];   // 64 MB
__device__ __align__(1024) __half g_rwh[2][3072 * 1024];    // 24 MB
__device__ __align__(1024) __half g_rwoh[2][1024 * 1024];   // 8 MB

// ---------------------------------------------------------------------------
// helpers
// ---------------------------------------------------------------------------
DEVINL void mma_h(float* c, const uint32_t* a, uint32_t b0, uint32_t b1) {
    asm("mma.sync.aligned.m16n8k16.row.col.f32.f16.f16.f32 "
        "{%0,%1,%2,%3}, {%4,%5,%6,%7}, {%8,%9}, {%0,%1,%2,%3};"
        : "+f"(c[0]), "+f"(c[1]), "+f"(c[2]), "+f"(c[3])
        : "r"(a[0]), "r"(a[1]), "r"(a[2]), "r"(a[3]), "r"(b0), "r"(b1));
}
DEVINL void ldsm4(uint32_t* r, uint32_t addr) {
    asm volatile("ldmatrix.sync.aligned.m8n8.x4.shared.b16 {%0,%1,%2,%3}, [%4];"
        : "=r"(r[0]), "=r"(r[1]), "=r"(r[2]), "=r"(r[3]) : "r"(addr));
}
DEVINL void ldsm4t(uint32_t* r, uint32_t addr) {
    asm volatile("ldmatrix.sync.aligned.m8n8.x4.trans.shared.b16 {%0,%1,%2,%3}, [%4];"
        : "=r"(r[0]), "=r"(r[1]), "=r"(r[2]), "=r"(r[3]) : "r"(addr));
}
DEVINL uint32_t smem_u32(const void* p) { return (uint32_t)__cvta_generic_to_shared(p); }
DEVINL void cp16(uint32_t dst, const void* src) {
    asm volatile("cp.async.ca.shared.global [%0], [%1], 16;" :: "r"(dst), "l"(src));
}
DEVINL void cp_commit() { asm volatile("cp.async.commit_group;"); }
template<int N> DEVINL void cp_wait() { asm volatile("cp.async.wait_group %0;" :: "n"(N)); }
DEVINL void sth2(__half* p, float a, float b) {
    __half2 h = __floats2half2_rn(a, b);
    *(uint32_t*)p = *(const uint32_t*)&h;
}

// ---------------------------------------------------------------------------
// fp32 -> fp16 conversion (RNE)
// ---------------------------------------------------------------------------
__global__ void to_half_k(const float4* __restrict__ in, uint2* __restrict__ out, int n4)
{
    int i = blockIdx.x * blockDim.x + threadIdx.x;
    if (i < n4) {
        float4 v = in[i];
        __half2 h0 = __floats2half2_rn(v.x, v.y);
        __half2 h1 = __floats2half2_rn(v.z, v.w);
        uint2 u;
        u.x = *(const uint32_t*)&h0;
        u.y = *(const uint32_t*)&h1;
        out[i] = u;
    }
}

// ---------------------------------------------------------------------------
// fp16 GEMM (r14, at SIMT ceiling): C[M,N] = A @ W^T + bias
// BM=128, BN=128, BK=64, 8 warps 32x64, ldmatrix, 2 CTAs/SM.
// ---------------------------------------------------------------------------
__global__ void __launch_bounds__(256, 2)
gemm_h(const __half* __restrict__ A, int lda,
       const __half* __restrict__ W, int ldw,
       void* __restrict__ Cv, int ldc,
       int K, const float* __restrict__ bias, int half_out)
{
    constexpr int LDH = 72;
    extern __shared__ __half smh[];
    __half* As = smh;                    // [2][128][72]
    __half* Bs = smh + 2 * 128 * LDH;    // [2][128][72]

    const int tid = threadIdx.x, lane = tid & 31, wid = tid >> 5;
    const int warpM = (wid & 3) * 32, warpN = (wid >> 2) * 64;
    const long long m0 = (long long)blockIdx.y * 128;
    const long long n0 = (long long)blockIdx.x * 128;
    const int lr = lane & 15;
    const int lc = (lane >> 4) * 8;

    float acc[2][8][4] = {};

    auto issue = [&](int it, int buf) {
        const long long k0 = (long long)it * 64;
        __half* ad = As + buf * 128 * LDH;
        #pragma unroll
        for (int i = 0; i < 4; ++i) {
            int lin = i * 256 + tid;
            int r = lin >> 3, c8 = (lin & 7) * 8;
            cp16(smem_u32(ad + r * LDH + c8), A + (m0 + r) * lda + k0 + c8);
        }
        __half* bd = Bs + buf * 128 * LDH;
        #pragma unroll
        for (int i = 0; i < 4; ++i) {
            int lin = i * 256 + tid;
            int r = lin >> 3, c8 = (lin & 7) * 8;
            cp16(smem_u32(bd + r * LDH + c8), W + (n0 + r) * ldw + k0 + c8);
        }
        cp_commit();
    };

    const int NIT = K / 64;
    issue(0, 0);
    int buf = 0;
    for (int it = 0; it < NIT; ++it) {
        cp_wait<0>();
        __syncthreads();
        if (it + 1 < NIT) issue(it + 1, buf ^ 1);

        const __half* a = As + buf * 128 * LDH;
        const __half* b = Bs + buf * 128 * LDH;
        #pragma unroll
        for (int k16 = 0; k16 < 4; ++k16) {
            const int kb = k16 * 16 + lc;
            uint32_t af[2][4], bf[4][4];
            #pragma unroll
            for (int im = 0; im < 2; ++im)
                ldsm4(af[im], smem_u32(a + (warpM + im * 16 + lr) * LDH + kb));
            #pragma unroll
            for (int in = 0; in < 4; ++in)
                ldsm4(bf[in], smem_u32(b + (warpN + in * 16 + lr) * LDH + kb));
            #pragma unroll
            for (int in = 0; in < 4; ++in)
                #pragma unroll
                for (int im = 0; im < 2; ++im) {
                    mma_h(acc[im][2 * in],     af[im], bf[in][0], bf[in][2]);
                    mma_h(acc[im][2 * in + 1], af[im], bf[in][1], bf[in][3]);
                }
        }
        buf ^= 1;
    }

    #pragma unroll
    for (int im = 0; im < 2; ++im) {
        long long r = m0 + warpM + im * 16 + (lane >> 2);
        #pragma unroll
        for (int in = 0; in < 8; ++in) {
            long long c = n0 + warpN + in * 8 + 2 * (lane & 3);
            float b0 = bias[c], b1 = bias[c + 1];
            float v0 = acc[im][in][0] + b0, v1 = acc[im][in][1] + b1;
            float v2 = acc[im][in][2] + b0, v3 = acc[im][in][3] + b1;
            if (half_out) {
                __half* Ch = (__half*)Cv;
                sth2(Ch + r * ldc + c, v0, v1);
                sth2(Ch + (r + 8) * ldc + c, v2, v3);
            } else {
                float* Cf = (float*)Cv;
                *(float2*)&Cf[r * ldc + c]       = make_float2(v0, v1);
                *(float2*)&Cf[(r + 8) * ldc + c] = make_float2(v2, v3);
            }
        }
    }
}

// ---------------------------------------------------------------------------
// Fused fp16 attention, TM=16 for BOTH branches, 2 CTAs/SM so one CTA's
// softmax overlaps the other's MMA. 128-row Q-tiles, 64-key chunks.
// smem halves: sQ[128][72] | sP[128][72] | sK[2][64][72] | sV[2][64][72]
// ---------------------------------------------------------------------------
__global__ void __launch_bounds__(256, 2)
attn_h(const __half* __restrict__ qkv, __half* __restrict__ ao, int W, int nc)
{
    constexpr int LDH = 72;
    extern __shared__ __half smh[];
    __half* sQ = smh;                         // 128 x 72
    __half* sP = sQ + 128 * LDH;              // 128 x 72
    __half* sK = sP + 128 * LDH;              // 2 x 64 x 72
    __half* sV = sK + 2 * 64 * LDH;           // 2 x 64 x 72

    const int tid = threadIdx.x, lane = tid & 31, wid = tid >> 5;
    const int wm = wid * 16;
    const int lr = lane & 15, lc = (lane >> 4) * 8;
    const int vkr = (lane & 7) + ((lane >> 4) & 1) * 8;
    const int vdc = ((lane >> 3) & 1) * 8;
    const int pair = blockIdx.y;
    const int win = pair >> 4, h = pair & 15;
    const int q0 = blockIdx.x * 128;
    const long long base = (long long)win * W * 3072 + h * 64;
    const __half* Qg = qkv + base + (long long)q0 * 3072;
    const __half* Kg = qkv + base + 1024;
    const __half* Vg = qkv + base + 2048;

    // stage Q
    #pragma unroll
    for (int i = 0; i < 4; ++i) {
        int lin = i * 256 + tid;
        int r = lin >> 3, c8 = (lin & 7) * 8;
        cp16(smem_u32(sQ + r * LDH + c8), Qg + (long long)r * 3072 + c8);
    }
    cp_commit();

    auto stageKV = [&](int c, int b) {
        #pragma unroll
        for (int i = 0; i < 2; ++i) {
            int lin = i * 256 + tid;
            int r = lin >> 3, c8 = (lin & 7) * 8;
            cp16(smem_u32(sK + b * 64 * LDH + r * LDH + c8),
                 Kg + (long long)(c * 64 + r) * 3072 + c8);
        }
        #pragma unroll
        for (int i = 0; i < 2; ++i) {
            int lin = i * 256 + tid;
            int r = lin >> 3, c8 = (lin & 7) * 8;
            cp16(smem_u32(sV + b * 64 * LDH + r * LDH + c8),
                 Vg + (long long)(c * 64 + r) * 3072 + c8);
        }
        cp_commit();
    };
    stageKV(0, 0);

    // Q arrived -> hoist Q fragments
    cp_wait<1>();
    __syncthreads();
    uint32_t qf[4][4];
    #pragma unroll
    for (int k16 = 0; k16 < 4; ++k16)
        ldsm4(qf[k16], smem_u32(sQ + (wm + lr) * LDH + k16 * 16 + lc));

    float oacc[8][4] = {};
    float m_[2] = {-1e30f, -1e30f}, l_[2] = {0.f, 0.f};

    for (int c = 0; c < nc; ++c) {
        const int buf = c & 1;
        if (c + 1 < nc) { stageKV(c + 1, buf ^ 1); cp_wait<1>(); }
        else            { cp_wait<0>(); }
        __syncthreads();

        const __half* kbuf = sK + buf * 64 * LDH;
        const __half* vbuf = sV + buf * 64 * LDH;

        // ---- S = Q K^T ----
        float sacc[8][4];
        #pragma unroll
        for (int i = 0; i < 8; ++i)
            sacc[i][0] = sacc[i][1] = sacc[i][2] = sacc[i][3] = 0.f;

        #pragma unroll
        for (int k16 = 0; k16 < 4; ++k16) {
            const int kb = k16 * 16 + lc;
            #pragma unroll
            for (int nb = 0; nb < 4; ++nb) {
                uint32_t bf[4];
                ldsm4(bf, smem_u32(kbuf + (nb * 16 + lr) * LDH + kb));
                mma_h(sacc[2 * nb],     qf[k16], bf[0], bf[2]);
                mma_h(sacc[2 * nb + 1], qf[k16], bf[1], bf[3]);
            }
        }

        // ---- online softmax (ADDITIVE +1.0 mask for col > row) ----
        float sscale[2];
        #pragma unroll
        for (int hh = 0; hh < 2; ++hh) {
            const int rw = q0 + wm + (lane >> 2) + 8 * hh;
            float cm = -1e30f;
            #pragma unroll
            for (int in = 0; in < 8; ++in) {
                int col = c * 64 + in * 8 + 2 * (lane & 3);
                float v0 = sacc[in][2 * hh]     * 0.125f + ((col     > rw) ? 1.f : 0.f);
                float v1 = sacc[in][2 * hh + 1] * 0.125f + ((col + 1 > rw) ? 1.f : 0.f);
                sacc[in][2 * hh] = v0; sacc[in][2 * hh + 1] = v1;
                cm = fmaxf(cm, fmaxf(v0, v1));
            }
            cm = fmaxf(cm, __shfl_xor_sync(0xffffffffu, cm, 1));
            cm = fmaxf(cm, __shfl_xor_sync(0xffffffffu, cm, 2));
            float mn = fmaxf(m_[hh], cm);
            float sc = __expf(m_[hh] - mn);
            float rs = 0.f;
            const int rloc = wm + (lane >> 2) + 8 * hh;
            #pragma unroll
            for (int in = 0; in < 8; ++in) {
                float p0 = __expf(sacc[in][2 * hh] - mn);
                float p1 = __expf(sacc[in][2 * hh + 1] - mn);
                rs += p0 + p1;
                sth2(sP + rloc * LDH + in * 8 + 2 * (lane & 3), p0, p1);
            }
            rs += __shfl_xor_sync(0xffffffffu, rs, 1);
            rs += __shfl_xor_sync(0xffffffffu, rs, 2);
            l_[hh] = l_[hh] * sc + rs;
            m_[hh] = mn;
            sscale[hh] = sc;
        }
        #pragma unroll
        for (int in = 0; in < 8; ++in) {
            oacc[in][0] *= sscale[0]; oacc[in][1] *= sscale[0];
            oacc[in][2] *= sscale[1]; oacc[in][3] *= sscale[1];
        }
        __syncwarp();   // sP rows warp-private; ldmatrix reads cross-lane

        // ---- O += P V (V via ldmatrix.trans) ----
        #pragma unroll
        for (int k16 = 0; k16 < 4; ++k16) {
            const int kb = k16 * 16;
            uint32_t pf[4];
            ldsm4(pf, smem_u32(sP + (wm + lr) * LDH + kb + lc));
            #pragma unroll
            for (int d16 = 0; d16 < 4; ++d16) {
                uint32_t vf[4];
                ldsm4t(vf, smem_u32(vbuf + (kb + vkr) * LDH + d16 * 16 + vdc));
                mma_h(oacc[2 * d16],     pf, vf[0], vf[2]);
                mma_h(oacc[2 * d16 + 1], pf, vf[1], vf[3]);
            }
        }
        __syncthreads();
    }

    // ---- epilogue: O /= l -> fp16 ao ----
    #pragma unroll
    for (int hh = 0; hh < 2; ++hh) {
        const float inv = 1.f / l_[hh];
        const long long trow = (long long)win * W + q0 + wm + (lane >> 2) + 8 * hh;
        __half* Od = ao + trow * 1024 + h * 64;
        #pragma unroll
        for (int in = 0; in < 8; ++in) {
            int cc = in * 8 + 2 * (lane & 3);
            sth2(Od + cc, oacc[in][2 * hh] * inv, oacc[in][2 * hh + 1] * inv);
        }
    }
}

// ---------------------------------------------------------------------------
// driver
// ---------------------------------------------------------------------------
static const int GEMM_SMEM = 2 * (128 + 128) * 72 * 2;       // 73728
static const int ATTN_SMEM = (2 * 128 + 4 * 64) * 72 * 2;    // 73728

static void run_branch(cudaStream_t st, const float* x,
                       const float* w_in, const float* b_in,
                       const float* w_out, const float* b_out,
                       int W, float* out,
                       __half* qkv, __half* ao, __half* rX, __half* rW, __half* rWo)
{
    to_half_k<<<16384, 256, 0, st>>>((const float4*)x, (uint2*)rX, 16384 * 1024 / 4);
    to_half_k<<<3072, 256, 0, st>>>((const float4*)w_in, (uint2*)rW, 3072 * 1024 / 4);
    to_half_k<<<1024, 256, 0, st>>>((const float4*)w_out, (uint2*)rWo, 1024 * 1024 / 4);

    gemm_h<<<dim3(3072 / 128, 16384 / 128), 256, GEMM_SMEM, st>>>(
        rX, Dd, rW, Dd, qkv, 3072, Dd, b_in, 1);

    attn_h<<<dim3(W / 128, (16384 / W) * Hh), 256, ATTN_SMEM, st>>>(qkv, ao, W, W / 64);

    gemm_h<<<dim3(1024 / 128, 16384 / 128), 256, GEMM_SMEM, st>>>(
        ao, Dd, rWo, Dd, out, Dd, Dd, b_out, 0);
}

extern "C" void kernel_launch(void* const* d_in, const int* in_sizes, int n_in,
                              void* d_out, int out_size)
{
    const float* lqs    = (const float*)d_in[0];
    const float* gqs    = (const float*)d_in[1];
    const float* wl_in  = (const float*)d_in[2];
    const float* bl_in  = (const float*)d_in[3];
    const float* wl_out = (const float*)d_in[4];
    const float* bl_out = (const float*)d_in[5];
    const float* wg_in  = (const float*)d_in[6];
    const float* bg_in  = (const float*)d_in[7];
    const float* wg_out = (const float*)d_in[8];
    const float* bg_out = (const float*)d_in[9];
    float* out = (float*)d_out;

    static cudaStream_t s2 = nullptr;
    static cudaEvent_t eFork = nullptr, eJoin = nullptr;
    if (!s2) {
        cudaStreamCreateWithFlags(&s2, cudaStreamNonBlocking);
        cudaEventCreateWithFlags(&eFork, cudaEventDisableTiming);
        cudaEventCreateWithFlags(&eJoin, cudaEventDisableTiming);
    }

    cudaFuncSetAttribute(gemm_h, cudaFuncAttributeMaxDynamicSharedMemorySize, GEMM_SMEM);
    cudaFuncSetAttribute(attn_h, cudaFuncAttributeMaxDynamicSharedMemorySize, ATTN_SMEM);

    __half *qkv0, *ao0, *rX0, *rW0, *rWo0;
    cudaGetSymbolAddress((void**)&qkv0, g_qkvh);
    cudaGetSymbolAddress((void**)&ao0, g_aoh);
    cudaGetSymbolAddress((void**)&rX0, g_rxh);
    cudaGetSymbolAddress((void**)&rW0, g_rwh);
    cudaGetSymbolAddress((void**)&rWo0, g_rwoh);
    __half* qkv1 = qkv0 + (size_t)16384 * 3072;
    __half* ao1  = ao0  + (size_t)16384 * 1024;
    __half* rX1  = rX0  + (size_t)16384 * 1024;
    __half* rW1  = rW0  + (size_t)3072 * 1024;
    __half* rWo1 = rWo0 + (size_t)1024 * 1024;

    // fork: branch 0 (local) on default stream, branch 1 (global) on s2
    cudaEventRecord(eFork, 0);
    cudaStreamWaitEvent(s2, eFork, 0);

    run_branch(0,  lqs, wl_in, bl_in, wl_out, bl_out, 128, out,
               qkv0, ao0, rX0, rW0, rWo0);
    run_branch(s2, gqs, wg_in, bg_in, wg_out, bg_out, 1024,
               out + (size_t)Bb * Ss * Dd,
               qkv1, ao1, rX1, rW1, rWo1);

    // join
    cudaEventRecord(eJoin, s2);
    cudaStreamWaitEvent(0, eJoin, 0);
}